// round 14
// baseline (speedup 1.0000x reference)
#include <cuda_runtime.h>
#include <cuda_fp16.h>
#include <cstdint>

// RelationDistMult: out[N,C] = (query * M) @ class^T
// N=16384, C=1024, H=2048, fp32 in/out.
// Baseline tensor-core ISA (mma.sync m16n8k16 + ldmatrix + cp.async);
// tcgen05 unavailable (harness PTX target sm_103, not sm_103a).
//
// R14 change (vs R13: tensor=58.6%, occ=12.3% -> 2 warps/SMSP latency-bound):
//  512 threads = 16 warps (4M x 4N), warp tile 64x32, same 256x128 block tile.
//  ~115 regs/thread -> 1 CTA x 16 warps = 4 warps/SMSP: doubles latency hiding
//  for the LDSM->MMA dependency shadow at each k16 step.

#define N_Q 16384
#define C_CLS 1024
#define H_DIM 2048

#define BM 256
#define BN 128
#define BK 64                      // 64 fp16 = 128 bytes per row
#define KITERS (H_DIM / BK)        // 32

#define NSTAGES 3
#define A_STAGE_BYTES (BM * BK * 2)               // 32768
#define B_STAGE_BYTES (BN * BK * 2)               // 16384
#define STAGE_BYTES (A_STAGE_BYTES + B_STAGE_BYTES)   // 49152
#define SMEM_TOTAL (NSTAGES * STAGE_BYTES)            // 147456

// ---- scratch (device globals: allocation-free per harness rules) ----
__device__ __half g_A[(size_t)N_Q * H_DIM];    // 32 MB  (query, fp16)
__device__ __half g_B[(size_t)C_CLS * H_DIM];  // 2 MB   (class * M, fp16)

// ======================= PTX helpers =======================

__device__ __forceinline__ uint32_t smem_u32(const void* p) {
    uint32_t a;
    asm("{ .reg .u64 t; cvta.to.shared.u64 t, %1; cvt.u32.u64 %0, t; }"
        : "=r"(a) : "l"(p));
    return a;
}

__device__ __forceinline__ void cp16(uint32_t saddr, const void* gaddr) {
    asm volatile("cp.async.cg.shared.global [%0], [%1], 16;"
                 :: "r"(saddr), "l"(gaddr) : "memory");
}

__device__ __forceinline__ void ldm_x4(uint32_t& r0, uint32_t& r1,
                                       uint32_t& r2, uint32_t& r3, uint32_t addr) {
    asm volatile("ldmatrix.sync.aligned.m8n8.x4.shared.b16 {%0,%1,%2,%3}, [%4];"
                 : "=r"(r0), "=r"(r1), "=r"(r2), "=r"(r3) : "r"(addr));
}

__device__ __forceinline__ void mma16816(float& c0, float& c1, float& c2, float& c3,
                                         uint32_t a0, uint32_t a1, uint32_t a2, uint32_t a3,
                                         uint32_t b0, uint32_t b1) {
    asm volatile(
        "mma.sync.aligned.m16n8k16.row.col.f32.f16.f16.f32 "
        "{%0,%1,%2,%3}, {%4,%5,%6,%7}, {%8,%9}, {%0,%1,%2,%3};"
        : "+f"(c0), "+f"(c1), "+f"(c2), "+f"(c3)
        : "r"(a0), "r"(a1), "r"(a2), "r"(a3), "r"(b0), "r"(b1));
}

// ======================= merged prep kernel =======================

#define NA4 ((size_t)N_Q * H_DIM / 4)
#define NB4 ((size_t)C_CLS * H_DIM / 4)

__global__ void __launch_bounds__(256) prep_kernel(const float4* __restrict__ q,
                                                   const float4* __restrict__ cls,
                                                   const float4* __restrict__ Mv) {
    size_t i = (size_t)blockIdx.x * blockDim.x + threadIdx.x;
    if (i < NA4) {
        float4 v = q[i];
        __half2* o = reinterpret_cast<__half2*>(g_A);
        o[2 * i]     = __floats2half2_rn(v.x, v.y);
        o[2 * i + 1] = __floats2half2_rn(v.z, v.w);
    } else if (i < NA4 + NB4) {
        size_t j = i - NA4;
        float4 m = Mv[j & (H_DIM / 4 - 1)];
        float4 v = cls[j];
        __half2* o = reinterpret_cast<__half2*>(g_B);
        o[2 * j]     = __floats2half2_rn(v.x * m.x, v.y * m.y);
        o[2 * j + 1] = __floats2half2_rn(v.z * m.z, v.w * m.w);
    }
}

// ======================= GEMM kernel =======================
// 512 threads = 16 warps: warp_m = wid&3 (64 rows each), warp_n = wid>>2
// (32 cols each). Warp tile 64x32, block tile 256x128.
// SMEM tiles: row-major, 128B rows, swizzle: colb ^= (row&7)<<4.

__global__ void __launch_bounds__(512, 1) gemm_kernel(float* __restrict__ out) {
    extern __shared__ char smem[];
    const uint32_t smem_base = smem_u32(smem);
    const int tid = threadIdx.x;
    const int wid = tid >> 5;
    const int lid = tid & 31;
    const int warp_m = wid & 3;       // 0..3  (64 rows each)
    const int warp_n = wid >> 2;      // 0..3  (32 cols each)
    const int n_base = blockIdx.x * BN;
    const int m_base = blockIdx.y * BM;

    // ---- conflict-free loader: row = tid>>3 (0..63), chunk j = tid&7 ----
    const int lrow = tid >> 3;
    const int lj = tid & 7;
    const uint32_t sw_j = ((uint32_t)(lj * 16)) ^ ((uint32_t)(lrow & 7) << 4);
    const char* gA_base = (const char*)(g_A + (size_t)(m_base + lrow) * H_DIM) + lj * 16;
    const char* gB_base = (const char*)(g_B + (size_t)(n_base + lrow) * H_DIM) + lj * 16;
    const uint32_t sA_base = (uint32_t)lrow * 128 + sw_j;                  // within A region
    const uint32_t sB_base = A_STAGE_BYTES + (uint32_t)lrow * 128 + sw_j;  // within stage

    auto issue_load = [&](int kk, int buf) {
        const uint32_t stage = smem_base + (uint32_t)buf * STAGE_BYTES;
        const size_t gk = (size_t)kk * 128;    // byte offset along K
#pragma unroll
        for (int p = 0; p < 4; p++)    // A: 4 passes x 64 rows = 256 rows
            cp16(stage + sA_base + p * 8192,
                 gA_base + gk + (size_t)p * 64 * H_DIM * 2);
#pragma unroll
        for (int p = 0; p < 2; p++)    // B: 2 passes x 64 rows = 128 rows
            cp16(stage + sB_base + p * 8192,
                 gB_base + gk + (size_t)p * 64 * H_DIM * 2);
    };

    // ---- per-lane ldmatrix row/col components ----
    const int a_row_in = (lid & 15);
    const int a_cl = (lid >> 4) * 16;
    const int b_row_in = (lid & 7) + ((lid >> 4) << 3);
    const int b_cl = (lid & 8) * 2;

    float acc[4][4][4];
#pragma unroll
    for (int i = 0; i < 4; i++)
#pragma unroll
        for (int j = 0; j < 4; j++) {
            acc[i][j][0] = 0.f; acc[i][j][1] = 0.f;
            acc[i][j][2] = 0.f; acc[i][j][3] = 0.f;
        }

    // prologue: fill 2 of 3 stages
#pragma unroll
    for (int s = 0; s < 2; s++) {
        issue_load(s, s);
        asm volatile("cp.async.commit_group;" ::: "memory");
    }

    for (int it = 0; it < KITERS; it++) {
        const int buf = it % NSTAGES;
        asm volatile("cp.async.wait_group 1;" ::: "memory");
        __syncthreads();   // stage `it` visible; stage it-1 fully consumed

        // prefetch it+2 into the freed stage
        const int nk = it + 2;
        if (nk < KITERS) issue_load(nk, nk % NSTAGES);
        asm volatile("cp.async.commit_group;" ::: "memory");

        const uint32_t sa = smem_base + (uint32_t)buf * STAGE_BYTES;
        const uint32_t sb = sa + A_STAGE_BYTES;

#pragma unroll
        for (int ks = 0; ks < 4; ks++) {
            const int kb = ks * 32;     // byte offset of this k16 step
            uint32_t a[4][4];
#pragma unroll
            for (int mt = 0; mt < 4; mt++) {
                const int row = warp_m * 64 + mt * 16 + a_row_in;
                const uint32_t colb = (uint32_t)(kb + a_cl) ^ ((uint32_t)(row & 7) << 4);
                ldm_x4(a[mt][0], a[mt][1], a[mt][2], a[mt][3],
                       sa + (uint32_t)row * 128 + colb);
            }
            uint32_t b[4][2];
#pragma unroll
            for (int p = 0; p < 2; p++) {
                const int row = warp_n * 32 + p * 16 + b_row_in;
                const uint32_t colb = (uint32_t)(kb + b_cl) ^ ((uint32_t)(row & 7) << 4);
                uint32_t r0, r1, r2, r3;
                ldm_x4(r0, r1, r2, r3, sb + (uint32_t)row * 128 + colb);
                b[2 * p][0] = r0; b[2 * p][1] = r1;
                b[2 * p + 1][0] = r2; b[2 * p + 1][1] = r3;
            }
#pragma unroll
            for (int mt = 0; mt < 4; mt++)
#pragma unroll
                for (int nt = 0; nt < 4; nt++)
                    mma16816(acc[mt][nt][0], acc[mt][nt][1],
                             acc[mt][nt][2], acc[mt][nt][3],
                             a[mt][0], a[mt][1], a[mt][2], a[mt][3],
                             b[nt][0], b[nt][1]);
        }
    }

    // ---- epilogue: registers -> gmem ----
    const int gid = lid >> 2;
    const int tid4 = lid & 3;
#pragma unroll
    for (int mt = 0; mt < 4; mt++) {
        const int r0 = m_base + warp_m * 64 + mt * 16 + gid;
#pragma unroll
        for (int nt = 0; nt < 4; nt++) {
            const int col = n_base + warp_n * 32 + nt * 8 + tid4 * 2;
            float2 v0 = make_float2(acc[mt][nt][0], acc[mt][nt][1]);
            float2 v1 = make_float2(acc[mt][nt][2], acc[mt][nt][3]);
            *reinterpret_cast<float2*>(out + (size_t)r0 * C_CLS + col) = v0;
            *reinterpret_cast<float2*>(out + (size_t)(r0 + 8) * C_CLS + col) = v1;
        }
    }
}

// ======================= host launch =======================

extern "C" void kernel_launch(void* const* d_in, const int* in_sizes, int n_in,
                              void* d_out, int out_size) {
    const float* cls = (const float*)d_in[0];   // class_vector (C, H)
    const float* q   = (const float*)d_in[1];   // query_encoder (N, H)
    const float* M   = (const float*)d_in[2];   // M (H, 1)
    float* out = (float*)d_out;

    (void)in_sizes; (void)n_in; (void)out_size;

    const size_t total4 = NA4 + NB4;
    prep_kernel<<<(unsigned)((total4 + 255) / 256), 256>>>(
        (const float4*)q, (const float4*)cls, (const float4*)M);

    cudaFuncSetAttribute(gemm_kernel,
                         cudaFuncAttributeMaxDynamicSharedMemorySize, SMEM_TOTAL);
    gemm_kernel<<<dim3(C_CLS / BN, N_Q / BM), 512, SMEM_TOTAL>>>(out);
}

// round 16
// speedup vs baseline: 1.0566x; 1.0566x over previous
#include <cuda_runtime.h>
#include <cuda_fp16.h>
#include <cstdint>

// RelationDistMult: out[N,C] = (query * M) @ class^T
// N=16384, C=1024, H=2048, fp32 in/out.
// Baseline tensor-core ISA (mma.sync m16n8k16 + ldmatrix + cp.async);
// tcgen05 unavailable (harness PTX target sm_103, not sm_103a).
//
// R16 = R15 with the OOB fix: epoch K-offset is e*256 bytes (2 sub-tiles x
// 64 fp16 = 256B), not e*512. R15's epoch-coarsening theory (one
// wait+__syncthreads per 128 K-elems, 16 epochs instead of 32) is otherwise
// unchanged: 2 stages x 96KB double-buffer, compute config identical to R13
// (256 thr, 8 warps, 64x64 warp tiles, conflict-free cp.async loader).

#define N_Q 16384
#define C_CLS 1024
#define H_DIM 2048

#define BM 256
#define BN 128
#define BK 64                        // one sub-tile: 64 fp16 = 128B per row
#define NEPOCH (H_DIM / (2 * BK))    // 16 epochs, 2 sub-tiles each

#define A_SUB_BYTES (BM * BK * 2)                 // 32768
#define B_SUB_BYTES (BN * BK * 2)                 // 16384
#define SUB_BYTES (A_SUB_BYTES + B_SUB_BYTES)     // 49152
#define STAGE_BYTES (2 * SUB_BYTES)               // 98304
#define SMEM_TOTAL (2 * STAGE_BYTES)              // 196608

// ---- scratch (device globals: allocation-free per harness rules) ----
__device__ __half g_A[(size_t)N_Q * H_DIM];    // 64 MB  (query, fp16)
__device__ __half g_B[(size_t)C_CLS * H_DIM];  // 4 MB   (class * M, fp16)

// ======================= PTX helpers =======================

__device__ __forceinline__ uint32_t smem_u32(const void* p) {
    uint32_t a;
    asm("{ .reg .u64 t; cvta.to.shared.u64 t, %1; cvt.u32.u64 %0, t; }"
        : "=r"(a) : "l"(p));
    return a;
}

__device__ __forceinline__ void cp16(uint32_t saddr, const void* gaddr) {
    asm volatile("cp.async.cg.shared.global [%0], [%1], 16;"
                 :: "r"(saddr), "l"(gaddr) : "memory");
}

__device__ __forceinline__ void ldm_x4(uint32_t& r0, uint32_t& r1,
                                       uint32_t& r2, uint32_t& r3, uint32_t addr) {
    asm volatile("ldmatrix.sync.aligned.m8n8.x4.shared.b16 {%0,%1,%2,%3}, [%4];"
                 : "=r"(r0), "=r"(r1), "=r"(r2), "=r"(r3) : "r"(addr));
}

__device__ __forceinline__ void mma16816(float& c0, float& c1, float& c2, float& c3,
                                         uint32_t a0, uint32_t a1, uint32_t a2, uint32_t a3,
                                         uint32_t b0, uint32_t b1) {
    asm volatile(
        "mma.sync.aligned.m16n8k16.row.col.f32.f16.f16.f32 "
        "{%0,%1,%2,%3}, {%4,%5,%6,%7}, {%8,%9}, {%0,%1,%2,%3};"
        : "+f"(c0), "+f"(c1), "+f"(c2), "+f"(c3)
        : "r"(a0), "r"(a1), "r"(a2), "r"(a3), "r"(b0), "r"(b1));
}

// ======================= merged prep kernel =======================

#define NA4 ((size_t)N_Q * H_DIM / 4)
#define NB4 ((size_t)C_CLS * H_DIM / 4)

__global__ void __launch_bounds__(256) prep_kernel(const float4* __restrict__ q,
                                                   const float4* __restrict__ cls,
                                                   const float4* __restrict__ Mv) {
    size_t i = (size_t)blockIdx.x * blockDim.x + threadIdx.x;
    if (i < NA4) {
        float4 v = q[i];
        __half2* o = reinterpret_cast<__half2*>(g_A);
        o[2 * i]     = __floats2half2_rn(v.x, v.y);
        o[2 * i + 1] = __floats2half2_rn(v.z, v.w);
    } else if (i < NA4 + NB4) {
        size_t j = i - NA4;
        float4 m = Mv[j & (H_DIM / 4 - 1)];
        float4 v = cls[j];
        __half2* o = reinterpret_cast<__half2*>(g_B);
        o[2 * j]     = __floats2half2_rn(v.x * m.x, v.y * m.y);
        o[2 * j + 1] = __floats2half2_rn(v.z * m.z, v.w * m.w);
    }
}

// ======================= GEMM kernel =======================
// 256 threads = 8 warps: warp_m = wid&3 (64 rows each), warp_n = wid>>2
// (64 cols each). Warp tile 64x64, block tile 256x128.
// SMEM sub-tiles: row-major, 128B rows, swizzle: colb ^= (row&7)<<4.
// Stage = [A sub0 | B sub0 | A sub1 | B sub1], 2 stages double-buffered.

__global__ void __launch_bounds__(256, 1) gemm_kernel(float* __restrict__ out) {
    extern __shared__ char smem[];
    const uint32_t smem_base = smem_u32(smem);
    const int tid = threadIdx.x;
    const int wid = tid >> 5;
    const int lid = tid & 31;
    const int warp_m = wid & 3;       // 0..3  (64 rows each)
    const int warp_n = wid >> 2;      // 0..1  (64 cols each)
    const int n_base = blockIdx.x * BN;
    const int m_base = blockIdx.y * BM;

    // ---- conflict-free loader layout: row = tid>>3 (0..31), chunk j = tid&7
    const int lrow = tid >> 3;
    const int lj = tid & 7;
    const uint32_t sw_j = ((uint32_t)(lj * 16)) ^ ((uint32_t)(lrow & 7) << 4);
    const char* gA_base = (const char*)(g_A + (size_t)(m_base + lrow) * H_DIM) + lj * 16;
    const char* gB_base = (const char*)(g_B + (size_t)(n_base + lrow) * H_DIM) + lj * 16;
    const uint32_t sA_base = (uint32_t)lrow * 128 + sw_j;               // within A sub
    const uint32_t sB_base = A_SUB_BYTES + (uint32_t)lrow * 128 + sw_j; // within sub

    // load one full epoch (two 64-K sub-tiles) into stage `buf`
    auto issue_epoch = [&](int e, int buf) {
        const uint32_t stage = smem_base + (uint32_t)buf * STAGE_BYTES;
#pragma unroll
        for (int sub = 0; sub < 2; sub++) {
            const uint32_t sbase = stage + (uint32_t)sub * SUB_BYTES;
            // bytes along K: one epoch = 2*BK = 128 K-elems = 256 bytes
            const size_t gk = (size_t)e * 256 + (size_t)sub * 128;
#pragma unroll
            for (int p = 0; p < 8; p++)    // A: 8 passes x 32 rows = 256 rows
                cp16(sbase + sA_base + p * 4096,
                     gA_base + gk + (size_t)p * 32 * H_DIM * 2);
#pragma unroll
            for (int p = 0; p < 4; p++)    // B: 4 passes x 32 rows = 128 rows
                cp16(sbase + sB_base + p * 4096,
                     gB_base + gk + (size_t)p * 32 * H_DIM * 2);
        }
    };

    // ---- per-lane ldmatrix row/col components ----
    const int a_row_in = (lid & 15);
    const int a_cl = (lid >> 4) * 16;
    const int b_row_in = (lid & 7) + ((lid >> 4) << 3);
    const int b_cl = (lid & 8) * 2;

    float acc[4][8][4];
#pragma unroll
    for (int i = 0; i < 4; i++)
#pragma unroll
        for (int j = 0; j < 8; j++) {
            acc[i][j][0] = 0.f; acc[i][j][1] = 0.f;
            acc[i][j][2] = 0.f; acc[i][j][3] = 0.f;
        }

    // prologue: load epoch 0 into stage 0
    issue_epoch(0, 0);
    asm volatile("cp.async.commit_group;" ::: "memory");

    for (int e = 0; e < NEPOCH; e++) {
        const int buf = e & 1;
        // data for epoch e was committed one full epoch ago
        asm volatile("cp.async.wait_group 0;" ::: "memory");
        __syncthreads();   // visibility; stage buf^1 fully consumed by all warps

        // prefetch next epoch into the freed stage
        if (e + 1 < NEPOCH) {
            issue_epoch(e + 1, buf ^ 1);
            asm volatile("cp.async.commit_group;" ::: "memory");
        }

        const uint32_t stage = smem_base + (uint32_t)buf * STAGE_BYTES;

#pragma unroll
        for (int sub = 0; sub < 2; sub++) {
            const uint32_t sa = stage + (uint32_t)sub * SUB_BYTES;
            const uint32_t sb = sa + A_SUB_BYTES;
#pragma unroll
            for (int ks = 0; ks < 4; ks++) {
                const int kb = ks * 32;     // byte offset of this k16 step
                uint32_t a[4][4];
#pragma unroll
                for (int mt = 0; mt < 4; mt++) {
                    const int row = warp_m * 64 + mt * 16 + a_row_in;
                    const uint32_t colb =
                        (uint32_t)(kb + a_cl) ^ ((uint32_t)(row & 7) << 4);
                    ldm_x4(a[mt][0], a[mt][1], a[mt][2], a[mt][3],
                           sa + (uint32_t)row * 128 + colb);
                }
                uint32_t b[8][2];
#pragma unroll
                for (int p = 0; p < 4; p++) {
                    const int row = warp_n * 64 + p * 16 + b_row_in;
                    const uint32_t colb =
                        (uint32_t)(kb + b_cl) ^ ((uint32_t)(row & 7) << 4);
                    uint32_t r0, r1, r2, r3;
                    ldm_x4(r0, r1, r2, r3, sb + (uint32_t)row * 128 + colb);
                    b[2 * p][0] = r0; b[2 * p][1] = r1;
                    b[2 * p + 1][0] = r2; b[2 * p + 1][1] = r3;
                }
#pragma unroll
                for (int mt = 0; mt < 4; mt++)
#pragma unroll
                    for (int nt = 0; nt < 8; nt++)
                        mma16816(acc[mt][nt][0], acc[mt][nt][1],
                                 acc[mt][nt][2], acc[mt][nt][3],
                                 a[mt][0], a[mt][1], a[mt][2], a[mt][3],
                                 b[nt][0], b[nt][1]);
            }
        }
    }

    // ---- epilogue: registers -> gmem ----
    const int gid = lid >> 2;
    const int tid4 = lid & 3;
#pragma unroll
    for (int mt = 0; mt < 4; mt++) {
        const int r0 = m_base + warp_m * 64 + mt * 16 + gid;
#pragma unroll
        for (int nt = 0; nt < 8; nt++) {
            const int col = n_base + warp_n * 64 + nt * 8 + tid4 * 2;
            float2 v0 = make_float2(acc[mt][nt][0], acc[mt][nt][1]);
            float2 v1 = make_float2(acc[mt][nt][2], acc[mt][nt][3]);
            *reinterpret_cast<float2*>(out + (size_t)r0 * C_CLS + col) = v0;
            *reinterpret_cast<float2*>(out + (size_t)(r0 + 8) * C_CLS + col) = v1;
        }
    }
}

// ======================= host launch =======================

extern "C" void kernel_launch(void* const* d_in, const int* in_sizes, int n_in,
                              void* d_out, int out_size) {
    const float* cls = (const float*)d_in[0];   // class_vector (C, H)
    const float* q   = (const float*)d_in[1];   // query_encoder (N, H)
    const float* M   = (const float*)d_in[2];   // M (H, 1)
    float* out = (float*)d_out;

    (void)in_sizes; (void)n_in; (void)out_size;

    const size_t total4 = NA4 + NB4;
    prep_kernel<<<(unsigned)((total4 + 255) / 256), 256>>>(
        (const float4*)q, (const float4*)cls, (const float4*)M);

    cudaFuncSetAttribute(gemm_kernel,
                         cudaFuncAttributeMaxDynamicSharedMemorySize, SMEM_TOTAL);
    gemm_kernel<<<dim3(C_CLS / BN, N_Q / BM), 256, SMEM_TOTAL>>>(out);
}

// round 17
// speedup vs baseline: 1.1183x; 1.0584x over previous
#include <cuda_runtime.h>
#include <cuda_fp16.h>
#include <cstdint>

// RelationDistMult: out[N,C] = (query * M) @ class^T
// N=16384, C=1024, H=2048, fp32 in/out.
// Baseline tensor-core ISA (mma.sync m16n8k16 + ldmatrix + cp.async);
// tcgen05 unavailable (harness PTX target sm_103, not sm_103a).
//
// R17 (vs R16 186us GEMM, tensor 60.6%): dominant identified loss was wave
// quantization (512 tiles / 148 SMs = 3.46 waves -> 13.5%). This round:
// BM=128 x BN=128 -> 1024 tiles, PERSISTENT grid of 148 CTAs, CTA c does
// tiles c+148i (7 vs 6 tiles -> 1.2% imbalance). Continuous 2-stage cp.async
// pipeline across tile boundaries hides inter-tile prologue/epilogue tails.
// Warp tile 64x32 (8 warps, 2M x 4N).

#define N_Q 16384
#define C_CLS 1024
#define H_DIM 2048

#define BM 128
#define BN 128
#define BK 64                        // one sub-tile: 64 fp16 = 128B per row
#define EPT 16                       // epochs per tile (2 subs = 128 K each)
#define NTILES ((N_Q / BM) * (C_CLS / BN))   // 1024
#define NCTA 148

#define A_SUB_BYTES (BM * BK * 2)                 // 16384
#define B_SUB_BYTES (BN * BK * 2)                 // 16384
#define SUB_BYTES (A_SUB_BYTES + B_SUB_BYTES)     // 32768
#define STAGE_BYTES (2 * SUB_BYTES)               // 65536
#define SMEM_TOTAL (2 * STAGE_BYTES)              // 131072

// ---- scratch (device globals: allocation-free per harness rules) ----
__device__ __half g_A[(size_t)N_Q * H_DIM];    // 64 MB  (query, fp16)
__device__ __half g_B[(size_t)C_CLS * H_DIM];  // 4 MB   (class * M, fp16)

// ======================= PTX helpers =======================

__device__ __forceinline__ uint32_t smem_u32(const void* p) {
    uint32_t a;
    asm("{ .reg .u64 t; cvta.to.shared.u64 t, %1; cvt.u32.u64 %0, t; }"
        : "=r"(a) : "l"(p));
    return a;
}

__device__ __forceinline__ void cp16(uint32_t saddr, const void* gaddr) {
    asm volatile("cp.async.cg.shared.global [%0], [%1], 16;"
                 :: "r"(saddr), "l"(gaddr) : "memory");
}

__device__ __forceinline__ void ldm_x4(uint32_t& r0, uint32_t& r1,
                                       uint32_t& r2, uint32_t& r3, uint32_t addr) {
    asm volatile("ldmatrix.sync.aligned.m8n8.x4.shared.b16 {%0,%1,%2,%3}, [%4];"
                 : "=r"(r0), "=r"(r1), "=r"(r2), "=r"(r3) : "r"(addr));
}

__device__ __forceinline__ void mma16816(float& c0, float& c1, float& c2, float& c3,
                                         uint32_t a0, uint32_t a1, uint32_t a2, uint32_t a3,
                                         uint32_t b0, uint32_t b1) {
    asm volatile(
        "mma.sync.aligned.m16n8k16.row.col.f32.f16.f16.f32 "
        "{%0,%1,%2,%3}, {%4,%5,%6,%7}, {%8,%9}, {%0,%1,%2,%3};"
        : "+f"(c0), "+f"(c1), "+f"(c2), "+f"(c3)
        : "r"(a0), "r"(a1), "r"(a2), "r"(a3), "r"(b0), "r"(b1));
}

// ======================= merged prep kernel =======================

#define NA4 ((size_t)N_Q * H_DIM / 4)
#define NB4 ((size_t)C_CLS * H_DIM / 4)

__global__ void __launch_bounds__(256) prep_kernel(const float4* __restrict__ q,
                                                   const float4* __restrict__ cls,
                                                   const float4* __restrict__ Mv) {
    size_t i = (size_t)blockIdx.x * blockDim.x + threadIdx.x;
    if (i < NA4) {
        float4 v = q[i];
        __half2* o = reinterpret_cast<__half2*>(g_A);
        o[2 * i]     = __floats2half2_rn(v.x, v.y);
        o[2 * i + 1] = __floats2half2_rn(v.z, v.w);
    } else if (i < NA4 + NB4) {
        size_t j = i - NA4;
        float4 m = Mv[j & (H_DIM / 4 - 1)];
        float4 v = cls[j];
        __half2* o = reinterpret_cast<__half2*>(g_B);
        o[2 * j]     = __floats2half2_rn(v.x * m.x, v.y * m.y);
        o[2 * j + 1] = __floats2half2_rn(v.z * m.z, v.w * m.w);
    }
}

// ======================= GEMM kernel (persistent) =======================
// 256 threads = 8 warps: warp_m = wid&1 (64 rows each), warp_n = wid>>1
// (32 cols each). Warp tile 64x32, block tile 128x128.
// SMEM sub-tiles: row-major, 128B rows, swizzle: colb ^= (row&7)<<4.
// Stage = [A sub0 | B sub0 | A sub1 | B sub1], 2 stages double-buffered,
// one continuous epoch stream across all tiles owned by this CTA.

__global__ void __launch_bounds__(256, 1) gemm_kernel(float* __restrict__ out) {
    extern __shared__ char smem[];
    const uint32_t smem_base = smem_u32(smem);
    const int tid = threadIdx.x;
    const int wid = tid >> 5;
    const int lid = tid & 31;
    const int warp_m = wid & 1;       // 0..1  (64 rows each)
    const int warp_n = wid >> 1;      // 0..3  (32 cols each)
    const int cta = blockIdx.x;

    const int my_tiles = (NTILES - cta + NCTA - 1) / NCTA;   // 7 or 6
    const int total_e = my_tiles * EPT;

    // ---- conflict-free loader layout: row = tid>>3 (0..31), chunk j = tid&7
    const int lrow = tid >> 3;
    const int lj = tid & 7;
    const uint32_t sw_j = ((uint32_t)(lj * 16)) ^ ((uint32_t)(lrow & 7) << 4);
    const uint32_t sA_base = (uint32_t)lrow * 128 + sw_j;               // within A sub
    const uint32_t sB_base = A_SUB_BYTES + (uint32_t)lrow * 128 + sw_j; // within sub

    // load one epoch (two 64-K sub-tiles) of global epoch `ge` into stage buf
    auto issue_epoch = [&](int ge, int buf) {
        const int t = ge >> 4;            // local tile index
        const int e = ge & (EPT - 1);     // epoch within tile
        const int ti = cta + t * NCTA;    // global tile id
        const int mb = (ti >> 3) * BM;
        const int nb = (ti & 7) * BN;
        const char* gA = (const char*)(g_A + (size_t)(mb + lrow) * H_DIM)
                         + lj * 16 + e * 256;
        const char* gB = (const char*)(g_B + (size_t)(nb + lrow) * H_DIM)
                         + lj * 16 + e * 256;
        const uint32_t stage = smem_base + (uint32_t)buf * STAGE_BYTES;
#pragma unroll
        for (int sub = 0; sub < 2; sub++) {
            const uint32_t sbase = stage + (uint32_t)sub * SUB_BYTES;
#pragma unroll
            for (int p = 0; p < 4; p++)    // A: 4 passes x 32 rows = 128 rows
                cp16(sbase + sA_base + p * 4096,
                     gA + sub * 128 + (size_t)p * 32 * H_DIM * 2);
#pragma unroll
            for (int p = 0; p < 4; p++)    // B: 4 passes x 32 rows = 128 rows
                cp16(sbase + sB_base + p * 4096,
                     gB + sub * 128 + (size_t)p * 32 * H_DIM * 2);
        }
    };

    // ---- per-lane ldmatrix row/col components ----
    const int a_row_in = (lid & 15);
    const int a_cl = (lid >> 4) * 16;
    const int b_row_in = (lid & 7) + ((lid >> 4) << 3);
    const int b_cl = (lid & 8) * 2;

    const int gid = lid >> 2;
    const int tid4 = lid & 3;

    float acc[4][4][4];
#pragma unroll
    for (int i = 0; i < 4; i++)
#pragma unroll
        for (int j = 0; j < 4; j++) {
            acc[i][j][0] = 0.f; acc[i][j][1] = 0.f;
            acc[i][j][2] = 0.f; acc[i][j][3] = 0.f;
        }

    // prologue: epoch 0 into stage 0
    issue_epoch(0, 0);
    asm volatile("cp.async.commit_group;" ::: "memory");

    for (int ge = 0; ge < total_e; ge++) {
        const int buf = ge & 1;
        asm volatile("cp.async.wait_group 0;" ::: "memory");
        __syncthreads();   // visibility; other stage fully consumed

        // prefetch next epoch (possibly next tile) into the freed stage
        if (ge + 1 < total_e) issue_epoch(ge + 1, buf ^ 1);
        asm volatile("cp.async.commit_group;" ::: "memory");

        const uint32_t stage = smem_base + (uint32_t)buf * STAGE_BYTES;

#pragma unroll
        for (int sub = 0; sub < 2; sub++) {
            const uint32_t sa = stage + (uint32_t)sub * SUB_BYTES;
            const uint32_t sb = sa + A_SUB_BYTES;
#pragma unroll
            for (int ks = 0; ks < 4; ks++) {
                const int kb = ks * 32;     // byte offset of this k16 step
                uint32_t a[4][4];
#pragma unroll
                for (int mt = 0; mt < 4; mt++) {
                    const int row = warp_m * 64 + mt * 16 + a_row_in;
                    const uint32_t colb =
                        (uint32_t)(kb + a_cl) ^ ((uint32_t)(row & 7) << 4);
                    ldm_x4(a[mt][0], a[mt][1], a[mt][2], a[mt][3],
                           sa + (uint32_t)row * 128 + colb);
                }
                uint32_t b[4][2];
#pragma unroll
                for (int p = 0; p < 2; p++) {
                    const int row = warp_n * 32 + p * 16 + b_row_in;
                    const uint32_t colb =
                        (uint32_t)(kb + b_cl) ^ ((uint32_t)(row & 7) << 4);
                    uint32_t r0, r1, r2, r3;
                    ldm_x4(r0, r1, r2, r3, sb + (uint32_t)row * 128 + colb);
                    b[2 * p][0] = r0; b[2 * p][1] = r1;
                    b[2 * p + 1][0] = r2; b[2 * p + 1][1] = r3;
                }
#pragma unroll
                for (int mt = 0; mt < 4; mt++)
#pragma unroll
                    for (int nt = 0; nt < 4; nt++)
                        mma16816(acc[mt][nt][0], acc[mt][nt][1],
                                 acc[mt][nt][2], acc[mt][nt][3],
                                 a[mt][0], a[mt][1], a[mt][2], a[mt][3],
                                 b[nt][0], b[nt][1]);
            }
        }

        // ---- tile boundary: drain accumulators, reset ----
        if ((ge & (EPT - 1)) == (EPT - 1)) {
            const int ti = cta + (ge >> 4) * NCTA;
            const int mb = (ti >> 3) * BM;
            const int nb = (ti & 7) * BN;
#pragma unroll
            for (int mt = 0; mt < 4; mt++) {
                const int r0 = mb + warp_m * 64 + mt * 16 + gid;
#pragma unroll
                for (int nt = 0; nt < 4; nt++) {
                    const int col = nb + warp_n * 32 + nt * 8 + tid4 * 2;
                    float2 v0 = make_float2(acc[mt][nt][0], acc[mt][nt][1]);
                    float2 v1 = make_float2(acc[mt][nt][2], acc[mt][nt][3]);
                    *reinterpret_cast<float2*>(out + (size_t)r0 * C_CLS + col) = v0;
                    *reinterpret_cast<float2*>(out + (size_t)(r0 + 8) * C_CLS + col) = v1;
                    acc[mt][nt][0] = 0.f; acc[mt][nt][1] = 0.f;
                    acc[mt][nt][2] = 0.f; acc[mt][nt][3] = 0.f;
                }
            }
        }
    }
}

// ======================= host launch =======================

extern "C" void kernel_launch(void* const* d_in, const int* in_sizes, int n_in,
                              void* d_out, int out_size) {
    const float* cls = (const float*)d_in[0];   // class_vector (C, H)
    const float* q   = (const float*)d_in[1];   // query_encoder (N, H)
    const float* M   = (const float*)d_in[2];   // M (H, 1)
    float* out = (float*)d_out;

    (void)in_sizes; (void)n_in; (void)out_size;

    const size_t total4 = NA4 + NB4;
    prep_kernel<<<(unsigned)((total4 + 255) / 256), 256>>>(
        (const float4*)q, (const float4*)cls, (const float4*)M);

    cudaFuncSetAttribute(gemm_kernel,
                         cudaFuncAttributeMaxDynamicSharedMemorySize, SMEM_TOTAL);
    gemm_kernel<<<NCTA, 256, SMEM_TOTAL>>>(out);
}